// round 11
// baseline (speedup 1.0000x reference)
#include <cuda_runtime.h>
#include <cuda_bf16.h>
#include <cstdint>

// Problem constants
#define BATCH 4096
#define DIM   4096
#define NBLK  16
#define SEC   256

// ---------------------------------------------------------------------------
// Scratch (static device globals; no runtime allocation allowed)
// ---------------------------------------------------------------------------
__device__ float g_h1[BATCH * DIM];                 // 64 MB layer1 out
__device__ float g_w2ct[NBLK * DIM];                // compact W2
__device__ float g_w3ct[NBLK * DIM];                // compact W3
__device__ __nv_bfloat16 g_xhi[(size_t)BATCH * DIM];  // 32 MB
__device__ __nv_bfloat16 g_xlo[(size_t)BATCH * DIM];  // 32 MB
__device__ __nv_bfloat16 g_wh[NBLK * SEC * SEC];      // 2 MB
__device__ __nv_bfloat16 g_wl[NBLK * SEC * SEC];      // 2 MB

__device__ __forceinline__ uint32_t smem_u32(const void* p) {
    uint32_t a;
    asm("{ .reg .u64 t; cvta.to.shared.u64 t, %1; cvt.u32.u64 %0, t; }"
        : "=r"(a) : "l"(p));
    return a;
}
__device__ __forceinline__ void cp_async16(uint32_t dst, const void* src) {
    asm volatile("cp.async.cg.shared.global [%0], [%1], 16;"
                 :: "r"(dst), "l"(src));
}
#define CP_COMMIT()  asm volatile("cp.async.commit_group;")
#define CP_WAIT(N)   asm volatile("cp.async.wait_group %0;" :: "n"(N))

// split one float4 into packed bf16x2 hi / lo pairs
__device__ __forceinline__ void split4(const float4 v, uint2& hi, uint2& lo)
{
    __nv_bfloat162 h01, h23, l01, l23;
    h01.x = __float2bfloat16(v.x);  h01.y = __float2bfloat16(v.y);
    h23.x = __float2bfloat16(v.z);  h23.y = __float2bfloat16(v.w);
    l01.x = __float2bfloat16(v.x - __bfloat162float(h01.x));
    l01.y = __float2bfloat16(v.y - __bfloat162float(h01.y));
    l23.x = __float2bfloat16(v.z - __bfloat162float(h23.x));
    l23.y = __float2bfloat16(v.w - __bfloat162float(h23.y));
    hi.x = *reinterpret_cast<uint32_t*>(&h01);
    hi.y = *reinterpret_cast<uint32_t*>(&h23);
    lo.x = *reinterpret_cast<uint32_t*>(&l01);
    lo.y = *reinterpret_cast<uint32_t*>(&l23);
}

__device__ __forceinline__ void ldmatrix_x4(
    uint32_t& r0, uint32_t& r1, uint32_t& r2, uint32_t& r3, uint32_t addr)
{
    asm volatile("ldmatrix.sync.aligned.m8n8.x4.shared.b16 {%0,%1,%2,%3}, [%4];"
                 : "=r"(r0), "=r"(r1), "=r"(r2), "=r"(r3) : "r"(addr));
}
__device__ __forceinline__ void mma_bf16(
    float* c, uint32_t a0, uint32_t a1, uint32_t a2, uint32_t a3,
    uint32_t b0, uint32_t b1)
{
    asm volatile(
        "mma.sync.aligned.m16n8k16.row.col.f32.bf16.bf16.f32 "
        "{%0,%1,%2,%3}, {%4,%5,%6,%7}, {%8,%9}, {%0,%1,%2,%3};"
        : "+f"(c[0]), "+f"(c[1]), "+f"(c[2]), "+f"(c[3])
        : "r"(a0), "r"(a1), "r"(a2), "r"(a3), "r"(b0), "r"(b1));
}

// ---------------------------------------------------------------------------
// Prep kernels
// ---------------------------------------------------------------------------
__global__ void pack_kernel(const float* __restrict__ W2,
                            const float* __restrict__ W3)
{
    int idx = blockIdx.x * 256 + threadIdx.x;
    if (idx >= NBLK * DIM) return;
    int k = idx >> 12;
    int o = idx & (DIM - 1);
    int c = o & (SEC - 1);
    float v2 = (k <= (o >> 8)) ? W2[o * DIM + k * SEC + c] : 0.0f;
    g_w2ct[idx] = v2;
    g_w3ct[idx] = W3[o * DIM + k * SEC + c];
}

// X -> bf16 hi/lo (memcpy-like, saturates HBM)
__global__ void __launch_bounds__(256) convert_x_kernel(const float* __restrict__ X)
{
    size_t i = (size_t)blockIdx.x * 256 + threadIdx.x;   // over 4M float4
    float4 v = reinterpret_cast<const float4*>(X)[i];
    uint2 hi, lo;
    split4(v, hi, lo);
    reinterpret_cast<uint2*>(g_xhi)[i] = hi;
    reinterpret_cast<uint2*>(g_xlo)[i] = lo;
}

// W1 diagonal blocks -> bf16 hi/lo, [z][row 0..255][k 0..255]
__global__ void __launch_bounds__(256) pack_w1_kernel(const float* __restrict__ W1)
{
    int idx = blockIdx.x * 256 + threadIdx.x;   // over 16*256*64 float4s
    int z  = idx >> 14;
    int r  = (idx >> 6) & 255;
    int c4 = idx & 63;
    float4 v = *reinterpret_cast<const float4*>(
        &W1[(size_t)(z * SEC + r) * DIM + z * SEC + c4 * 4]);
    uint2 hi, lo;
    split4(v, hi, lo);
    int o = (z * SEC + r) * SEC + c4 * 4;
    *reinterpret_cast<uint2*>(&g_wh[o]) = hi;
    *reinterpret_cast<uint2*>(&g_wl[o]) = lo;
}

// ---------------------------------------------------------------------------
// Layer 1: bf16x3 GEMM on mma.sync with cp.async double buffering.
// CTA tile 128x256 (M x N), BK=32, 512 threads = 16 warps (4m x 4n),
// warp tile 32x64. h1 = relu(X @ W1blk^T + b1), 16 independent sections.
// smem per buffer: A hi/lo 2x10240B + B hi/lo 2x20480B = 61440B; x2 = 120KB.
// ---------------------------------------------------------------------------
#define LDS       40                     // padded row stride (bf16 elements)
#define ROWB      (LDS * 2)              // 80 bytes per row
#define SMA_HI    0
#define SMA_LO    (128 * ROWB)           // 10240
#define SMB_HI    (2 * 128 * ROWB)       // 20480
#define SMB_LO    (SMB_HI + 256 * ROWB)  // 40960
#define BUFSZ     (SMB_LO + 256 * ROWB)  // 61440
#define SMEM_L1   (2 * BUFSZ)            // 122880

__device__ __forceinline__ void prefetch_chunk(
    uint32_t sbuf, int m0, int z, int k0, int tid)
{
    const int row   = tid >> 2;
    const int piece = tid & 3;
    // A tiles: 128 rows x 32 k
    {
        size_t src = (size_t)(m0 + row) * DIM + z * SEC + k0 + piece * 8;
        uint32_t dst = sbuf + row * ROWB + piece * 16;
        cp_async16(dst + SMA_HI, &g_xhi[src]);
        cp_async16(dst + SMA_LO, &g_xlo[src]);
    }
    // B tiles: 256 rows x 32 k
#pragma unroll
    for (int l = 0; l < 2; l++) {
        int idx = tid + 512 * l;
        int br  = idx >> 2;
        int bp  = idx & 3;
        size_t src = (size_t)(z * SEC + br) * SEC + k0 + bp * 8;
        uint32_t dst = sbuf + br * ROWB + bp * 16;
        cp_async16(dst + SMB_HI, &g_wh[src]);
        cp_async16(dst + SMB_LO, &g_wl[src]);
    }
}

__global__ void __launch_bounds__(512, 1) layer1_mma_kernel(
    const float* __restrict__ b1)
{
    extern __shared__ char dsm[];
    const uint32_t sbase = smem_u32(dsm);

    const int tid  = threadIdx.x;
    const int lane = tid & 31;
    const int wid  = tid >> 5;
    const int wm0  = (wid & 3) * 32;       // warp row base (0..96)
    const int wn0  = (wid >> 2) * 64;      // warp col base (0..192)
    const int m0   = blockIdx.x * 128;
    const int z    = blockIdx.y;

    float acc[2][8][4];
#pragma unroll
    for (int mi = 0; mi < 2; mi++)
#pragma unroll
        for (int ni = 0; ni < 8; ni++)
#pragma unroll
            for (int q = 0; q < 4; q++) acc[mi][ni][q] = 0.0f;

    // precomputed ldmatrix intra-warp offsets (bytes)
    const uint32_t a_off =
        ((lane & 15) * LDS + (lane >> 4) * 8) * 2;
    const uint32_t b_off =
        ((((lane >> 4) << 3) + (lane & 7)) * LDS + (((lane >> 3) & 1) << 3)) * 2;

    // prologue: prefetch chunk 0
    prefetch_chunk(sbase, m0, z, 0, tid);
    CP_COMMIT();

    for (int ch = 0; ch < SEC / 32; ch++) {
        if (ch + 1 < SEC / 32) {
            prefetch_chunk(sbase + ((ch + 1) & 1) * BUFSZ, m0, z, (ch + 1) * 32, tid);
            CP_COMMIT();
            CP_WAIT(1);
        } else {
            CP_WAIT(0);
        }
        __syncthreads();

        const uint32_t buf = sbase + (ch & 1) * BUFSZ;

#pragma unroll
        for (int pass = 0; pass < 3; pass++) {
            const uint32_t Ab = buf + ((pass == 1) ? SMA_LO : SMA_HI);
            const uint32_t Bb = buf + ((pass == 2) ? SMB_LO : SMB_HI);
#pragma unroll
            for (int ks = 0; ks < 2; ks++) {
                uint32_t a[2][4];
#pragma unroll
                for (int mi = 0; mi < 2; mi++) {
                    uint32_t addr = Ab + a_off +
                        ((wm0 + mi * 16) * LDS + ks * 16) * 2;
                    ldmatrix_x4(a[mi][0], a[mi][1], a[mi][2], a[mi][3], addr);
                }
                uint32_t b[4][4];
#pragma unroll
                for (int np = 0; np < 4; np++) {
                    uint32_t addr = Bb + b_off +
                        ((wn0 + np * 16) * LDS + ks * 16) * 2;
                    ldmatrix_x4(b[np][0], b[np][1], b[np][2], b[np][3], addr);
                }
#pragma unroll
                for (int mi = 0; mi < 2; mi++)
#pragma unroll
                    for (int ni = 0; ni < 8; ni++) {
                        int np = ni >> 1, h = (ni & 1) * 2;
                        mma_bf16(acc[mi][ni],
                                 a[mi][0], a[mi][1], a[mi][2], a[mi][3],
                                 b[np][h], b[np][h + 1]);
                    }
            }
        }
        __syncthreads();   // protect buffer overwrite next iteration
    }

    // ---- Epilogue: bias + ReLU, float2 stores
    const int g = lane >> 2;
    const int c = lane & 3;
#pragma unroll
    for (int mi = 0; mi < 2; mi++) {
        const int row0 = m0 + wm0 + mi * 16 + g;
        const int row1 = row0 + 8;
#pragma unroll
        for (int ni = 0; ni < 8; ni++) {
            const int col = z * SEC + wn0 + ni * 8 + 2 * c;
            const float bb0 = b1[col], bb1 = b1[col + 1];
            float2 v0, v1;
            v0.x = fmaxf(acc[mi][ni][0] + bb0, 0.0f);
            v0.y = fmaxf(acc[mi][ni][1] + bb1, 0.0f);
            v1.x = fmaxf(acc[mi][ni][2] + bb0, 0.0f);
            v1.y = fmaxf(acc[mi][ni][3] + bb1, 0.0f);
            *reinterpret_cast<float2*>(&g_h1[(size_t)row0 * DIM + col]) = v0;
            *reinterpret_cast<float2*>(&g_h1[(size_t)row1 * DIM + col]) = v1;
        }
    }
}

// ---------------------------------------------------------------------------
// FUSED layers 2+3 (unchanged): h2 lives only in shared memory.
// ---------------------------------------------------------------------------
#define FB_R    4
#define FB_BCNT 16

__global__ void __launch_bounds__(512) fused23_kernel(
    const float* __restrict__ b2,
    const float* __restrict__ b3,
    float* __restrict__ out)
{
    const int cx   = blockIdx.x;
    const int tid  = threadIdx.x;
    const int c    = tid & 63;
    const int gq   = tid >> 6;
    const int ccol = cx * 64 + c;

    __shared__ float h1s[FB_R][NBLK * 64];
    __shared__ float h2s[FB_R][NBLK * 64];

    float w2[2][NBLK], w3[2][NBLK], bv2[2], bv3[2];
#pragma unroll
    for (int u = 0; u < 2; u++) {
        int oy = gq * 2 + u;
        int o  = oy * SEC + ccol;
        bv2[u] = b2[o];
        bv3[u] = b3[o];
#pragma unroll
        for (int k = 0; k < NBLK; k++) {
            w2[u][k] = g_w2ct[k * DIM + o];
            w3[u][k] = g_w3ct[k * DIM + o];
        }
    }

    const int b0 = blockIdx.y * FB_BCNT;

    for (int s = 0; s < FB_BCNT; s += FB_R) {
#pragma unroll
        for (int l = 0; l < 2; l++) {
            int t  = tid + 512 * l;
            int r  = t >> 8;
            int q  = t & 255;
            int k  = q >> 4;
            int cc = (q & 15) * 4;
            float4 v = *reinterpret_cast<const float4*>(
                &g_h1[(size_t)(b0 + s + r) * DIM + k * SEC + cx * 64 + cc]);
            *reinterpret_cast<float4*>(&h1s[r][k * 64 + cc]) = v;
        }
        __syncthreads();

#pragma unroll
        for (int r = 0; r < FB_R; r++) {
            float iv[NBLK];
#pragma unroll
            for (int k = 0; k < NBLK; k++) iv[k] = h1s[r][k * 64 + c];
#pragma unroll
            for (int u = 0; u < 2; u++) {
                float acc = bv2[u];
#pragma unroll
                for (int k = 0; k < NBLK; k++)
                    acc = fmaf(w2[u][k], iv[k], acc);
                h2s[r][(gq * 2 + u) * 64 + c] = fmaxf(acc, 0.0f);
            }
        }
        __syncthreads();

#pragma unroll
        for (int r = 0; r < FB_R; r++) {
            float hv[NBLK];
#pragma unroll
            for (int k = 0; k < NBLK; k++) hv[k] = h2s[r][k * 64 + c];
#pragma unroll
            for (int u = 0; u < 2; u++) {
                float acc = bv3[u];
#pragma unroll
                for (int k = 0; k < NBLK; k++)
                    acc = fmaf(w3[u][k], hv[k], acc);
                out[(size_t)(b0 + s + r) * DIM + (gq * 2 + u) * SEC + ccol] = acc;
            }
        }
        __syncthreads();
    }
}

// ---------------------------------------------------------------------------
// Launch. Inputs (metadata order): x, W1, b1, W2, b2, W3, b3, m1, m2, m3
// ---------------------------------------------------------------------------
extern "C" void kernel_launch(void* const* d_in, const int* in_sizes, int n_in,
                              void* d_out, int out_size)
{
    const float* x  = (const float*)d_in[0];
    const float* W1 = (const float*)d_in[1];
    const float* b1 = (const float*)d_in[2];
    const float* W2 = (const float*)d_in[3];
    const float* b2 = (const float*)d_in[4];
    const float* W3 = (const float*)d_in[5];
    const float* b3 = (const float*)d_in[6];
    float* out = (float*)d_out;
    (void)in_sizes; (void)n_in; (void)out_size;

    static bool attr_set = false;
    if (!attr_set) {
        cudaFuncSetAttribute(layer1_mma_kernel,
                             cudaFuncAttributeMaxDynamicSharedMemorySize,
                             SMEM_L1);
        attr_set = true;
    }

    // 1) Prep: sparse tables + bf16 hi/lo packs
    pack_kernel<<<(NBLK * DIM + 255) / 256, 256>>>(W2, W3);
    pack_w1_kernel<<<(NBLK * SEC * 64) / 256, 256>>>(W1);
    convert_x_kernel<<<(int)(((size_t)BATCH * DIM / 4) / 256), 256>>>(x);

    // 2) Layer 1: double-buffered cp.async bf16x3 GEMM
    layer1_mma_kernel<<<dim3(BATCH / 128, NBLK), 512, SMEM_L1>>>(b1);

    // 3) Layers 2+3 fused
    fused23_kernel<<<dim3(4, BATCH / FB_BCNT), 512>>>(b2, b3, out);
}

// round 12
// speedup vs baseline: 1.0889x; 1.0889x over previous
#include <cuda_runtime.h>
#include <cuda_bf16.h>
#include <cstdint>

// Problem constants
#define BATCH 4096
#define DIM   4096
#define NBLK  16
#define SEC   256

// ---------------------------------------------------------------------------
// Scratch (static device globals; no runtime allocation allowed)
// ---------------------------------------------------------------------------
__device__ float g_h1[BATCH * DIM];                 // 64 MB layer1 out
__device__ float g_w2ct[NBLK * DIM];                // compact W2
__device__ float g_w3ct[NBLK * DIM];                // compact W3
__device__ __nv_bfloat16 g_xhi[(size_t)BATCH * DIM];  // 32 MB
__device__ __nv_bfloat16 g_xlo[(size_t)BATCH * DIM];  // 32 MB
__device__ __nv_bfloat16 g_wh[NBLK * SEC * SEC];      // 2 MB
__device__ __nv_bfloat16 g_wl[NBLK * SEC * SEC];      // 2 MB

__device__ __forceinline__ uint32_t smem_u32(const void* p) {
    uint32_t a;
    asm("{ .reg .u64 t; cvta.to.shared.u64 t, %1; cvt.u32.u64 %0, t; }"
        : "=r"(a) : "l"(p));
    return a;
}
__device__ __forceinline__ void cp_async16(uint32_t dst, const void* src) {
    asm volatile("cp.async.cg.shared.global [%0], [%1], 16;"
                 :: "r"(dst), "l"(src));
}
#define CP_COMMIT()  asm volatile("cp.async.commit_group;")
#define CP_WAIT(N)   asm volatile("cp.async.wait_group %0;" :: "n"(N))

// split one float4 into packed bf16x2 hi / lo pairs
__device__ __forceinline__ void split4(const float4 v, uint2& hi, uint2& lo)
{
    __nv_bfloat162 h01, h23, l01, l23;
    h01.x = __float2bfloat16(v.x);  h01.y = __float2bfloat16(v.y);
    h23.x = __float2bfloat16(v.z);  h23.y = __float2bfloat16(v.w);
    l01.x = __float2bfloat16(v.x - __bfloat162float(h01.x));
    l01.y = __float2bfloat16(v.y - __bfloat162float(h01.y));
    l23.x = __float2bfloat16(v.z - __bfloat162float(h23.x));
    l23.y = __float2bfloat16(v.w - __bfloat162float(h23.y));
    hi.x = *reinterpret_cast<uint32_t*>(&h01);
    hi.y = *reinterpret_cast<uint32_t*>(&h23);
    lo.x = *reinterpret_cast<uint32_t*>(&l01);
    lo.y = *reinterpret_cast<uint32_t*>(&l23);
}

__device__ __forceinline__ void ldmatrix_x4(
    uint32_t& r0, uint32_t& r1, uint32_t& r2, uint32_t& r3, uint32_t addr)
{
    asm volatile("ldmatrix.sync.aligned.m8n8.x4.shared.b16 {%0,%1,%2,%3}, [%4];"
                 : "=r"(r0), "=r"(r1), "=r"(r2), "=r"(r3) : "r"(addr));
}
__device__ __forceinline__ void mma_bf16(
    float* c, uint32_t a0, uint32_t a1, uint32_t a2, uint32_t a3,
    uint32_t b0, uint32_t b1)
{
    asm volatile(
        "mma.sync.aligned.m16n8k16.row.col.f32.bf16.bf16.f32 "
        "{%0,%1,%2,%3}, {%4,%5,%6,%7}, {%8,%9}, {%0,%1,%2,%3};"
        : "+f"(c[0]), "+f"(c[1]), "+f"(c[2]), "+f"(c[3])
        : "r"(a0), "r"(a1), "r"(a2), "r"(a3), "r"(b0), "r"(b1));
}

// ---------------------------------------------------------------------------
// Prep kernels
// ---------------------------------------------------------------------------
__global__ void pack_kernel(const float* __restrict__ W2,
                            const float* __restrict__ W3)
{
    int idx = blockIdx.x * 256 + threadIdx.x;
    if (idx >= NBLK * DIM) return;
    int k = idx >> 12;
    int o = idx & (DIM - 1);
    int c = o & (SEC - 1);
    float v2 = (k <= (o >> 8)) ? W2[o * DIM + k * SEC + c] : 0.0f;
    g_w2ct[idx] = v2;
    g_w3ct[idx] = W3[o * DIM + k * SEC + c];
}

// X -> bf16 hi/lo. 4 float4 in flight per thread (MLP=4) to saturate HBM.
__global__ void __launch_bounds__(256) convert_x_kernel(const float* __restrict__ X)
{
    size_t b0 = (size_t)blockIdx.x * 1024 + threadIdx.x;
    float4 v[4];
#pragma unroll
    for (int i = 0; i < 4; i++)
        v[i] = reinterpret_cast<const float4*>(X)[b0 + i * 256];
#pragma unroll
    for (int i = 0; i < 4; i++) {
        uint2 hi, lo;
        split4(v[i], hi, lo);
        reinterpret_cast<uint2*>(g_xhi)[b0 + i * 256] = hi;
        reinterpret_cast<uint2*>(g_xlo)[b0 + i * 256] = lo;
    }
}

// W1 diagonal blocks -> bf16 hi/lo, [z][row 0..255][k 0..255]
__global__ void __launch_bounds__(256) pack_w1_kernel(const float* __restrict__ W1)
{
    int idx = blockIdx.x * 256 + threadIdx.x;   // over 16*256*64 float4s
    int z  = idx >> 14;
    int r  = (idx >> 6) & 255;
    int c4 = idx & 63;
    float4 v = *reinterpret_cast<const float4*>(
        &W1[(size_t)(z * SEC + r) * DIM + z * SEC + c4 * 4]);
    uint2 hi, lo;
    split4(v, hi, lo);
    int o = (z * SEC + r) * SEC + c4 * 4;
    *reinterpret_cast<uint2*>(&g_wh[o]) = hi;
    *reinterpret_cast<uint2*>(&g_wl[o]) = lo;
}

// ---------------------------------------------------------------------------
// Layer 1: bf16x3 GEMM, mma.sync + cp.async double buffering.
// CTA tile 64x256 (M x N): N covers a whole section -> X read exactly once.
// 256 threads = 8 warps (2m x 4n), warp tile 32x64, BK=32.
// smem: per buffer A hi/lo 2x5120B + B hi/lo 2x20480B = 51200B; x2 = 100KB.
// 2 CTAs/SM for cross-CTA latency hiding.
// ---------------------------------------------------------------------------
#define LDS       40                     // padded row stride (bf16 elements)
#define ROWB      (LDS * 2)              // 80 bytes per row
#define SMA_HI    0
#define SMA_LO    (64 * ROWB)            // 5120
#define SMB_HI    (2 * 64 * ROWB)        // 10240
#define SMB_LO    (SMB_HI + 256 * ROWB)  // 30720
#define BUFSZ     (SMB_LO + 256 * ROWB)  // 51200
#define SMEM_L1   (2 * BUFSZ)            // 102400

__device__ __forceinline__ void prefetch_chunk(
    uint32_t sbuf, int m0, int z, int k0, int tid)
{
    const int row   = tid >> 2;          // 0..63
    const int piece = tid & 3;
    // A tiles: 64 rows x 32 k (hi + lo)
    {
        size_t src = (size_t)(m0 + row) * DIM + z * SEC + k0 + piece * 8;
        uint32_t dst = sbuf + row * ROWB + piece * 16;
        cp_async16(dst + SMA_HI, &g_xhi[src]);
        cp_async16(dst + SMA_LO, &g_xlo[src]);
    }
    // B tiles: 256 rows x 32 k (hi + lo)
#pragma unroll
    for (int l = 0; l < 4; l++) {
        int idx = tid + 256 * l;
        int br  = idx >> 2;
        int bp  = idx & 3;
        size_t src = (size_t)(z * SEC + br) * SEC + k0 + bp * 8;
        uint32_t dst = sbuf + br * ROWB + bp * 16;
        cp_async16(dst + SMB_HI, &g_wh[src]);
        cp_async16(dst + SMB_LO, &g_wl[src]);
    }
}

__global__ void __launch_bounds__(256, 2) layer1_mma_kernel(
    const float* __restrict__ b1)
{
    extern __shared__ char dsm[];
    const uint32_t sbase = smem_u32(dsm);

    const int tid  = threadIdx.x;
    const int lane = tid & 31;
    const int wid  = tid >> 5;
    const int wm0  = (wid & 1) * 32;       // warp row base (0 or 32)
    const int wn0  = (wid >> 1) * 64;      // warp col base (0..192)
    const int m0   = blockIdx.x * 64;
    const int z    = blockIdx.y;

    float acc[2][8][4];
#pragma unroll
    for (int mi = 0; mi < 2; mi++)
#pragma unroll
        for (int ni = 0; ni < 8; ni++)
#pragma unroll
            for (int q = 0; q < 4; q++) acc[mi][ni][q] = 0.0f;

    // ldmatrix intra-warp offsets (bytes)
    const uint32_t a_off =
        ((lane & 15) * LDS + (lane >> 4) * 8) * 2;
    const uint32_t b_off =
        ((((lane >> 4) << 3) + (lane & 7)) * LDS + (((lane >> 3) & 1) << 3)) * 2;

    prefetch_chunk(sbase, m0, z, 0, tid);
    CP_COMMIT();

    for (int ch = 0; ch < SEC / 32; ch++) {
        if (ch + 1 < SEC / 32) {
            prefetch_chunk(sbase + ((ch + 1) & 1) * BUFSZ, m0, z, (ch + 1) * 32, tid);
            CP_COMMIT();
            CP_WAIT(1);
        } else {
            CP_WAIT(0);
        }
        __syncthreads();

        const uint32_t buf = sbase + (ch & 1) * BUFSZ;

#pragma unroll
        for (int pass = 0; pass < 3; pass++) {
            const uint32_t Ab = buf + ((pass == 1) ? SMA_LO : SMA_HI);
            const uint32_t Bb = buf + ((pass == 2) ? SMB_LO : SMB_HI);
#pragma unroll
            for (int ks = 0; ks < 2; ks++) {
                uint32_t a[2][4];
#pragma unroll
                for (int mi = 0; mi < 2; mi++) {
                    uint32_t addr = Ab + a_off +
                        ((wm0 + mi * 16) * LDS + ks * 16) * 2;
                    ldmatrix_x4(a[mi][0], a[mi][1], a[mi][2], a[mi][3], addr);
                }
                uint32_t b[4][4];
#pragma unroll
                for (int np = 0; np < 4; np++) {
                    uint32_t addr = Bb + b_off +
                        ((wn0 + np * 16) * LDS + ks * 16) * 2;
                    ldmatrix_x4(b[np][0], b[np][1], b[np][2], b[np][3], addr);
                }
#pragma unroll
                for (int mi = 0; mi < 2; mi++)
#pragma unroll
                    for (int ni = 0; ni < 8; ni++) {
                        int np = ni >> 1, h = (ni & 1) * 2;
                        mma_bf16(acc[mi][ni],
                                 a[mi][0], a[mi][1], a[mi][2], a[mi][3],
                                 b[np][h], b[np][h + 1]);
                    }
            }
        }
        __syncthreads();   // protect buffer overwrite next iteration
    }

    // ---- Epilogue: bias + ReLU, float2 stores
    const int g = lane >> 2;
    const int c = lane & 3;
#pragma unroll
    for (int mi = 0; mi < 2; mi++) {
        const int row0 = m0 + wm0 + mi * 16 + g;
        const int row1 = row0 + 8;
#pragma unroll
        for (int ni = 0; ni < 8; ni++) {
            const int col = z * SEC + wn0 + ni * 8 + 2 * c;
            const float bb0 = b1[col], bb1 = b1[col + 1];
            float2 v0, v1;
            v0.x = fmaxf(acc[mi][ni][0] + bb0, 0.0f);
            v0.y = fmaxf(acc[mi][ni][1] + bb1, 0.0f);
            v1.x = fmaxf(acc[mi][ni][2] + bb0, 0.0f);
            v1.y = fmaxf(acc[mi][ni][3] + bb1, 0.0f);
            *reinterpret_cast<float2*>(&g_h1[(size_t)row0 * DIM + col]) = v0;
            *reinterpret_cast<float2*>(&g_h1[(size_t)row1 * DIM + col]) = v1;
        }
    }
}

// ---------------------------------------------------------------------------
// FUSED layers 2+3 (unchanged): h2 lives only in shared memory.
// ---------------------------------------------------------------------------
#define FB_R    4
#define FB_BCNT 16

__global__ void __launch_bounds__(512) fused23_kernel(
    const float* __restrict__ b2,
    const float* __restrict__ b3,
    float* __restrict__ out)
{
    const int cx   = blockIdx.x;
    const int tid  = threadIdx.x;
    const int c    = tid & 63;
    const int gq   = tid >> 6;
    const int ccol = cx * 64 + c;

    __shared__ float h1s[FB_R][NBLK * 64];
    __shared__ float h2s[FB_R][NBLK * 64];

    float w2[2][NBLK], w3[2][NBLK], bv2[2], bv3[2];
#pragma unroll
    for (int u = 0; u < 2; u++) {
        int oy = gq * 2 + u;
        int o  = oy * SEC + ccol;
        bv2[u] = b2[o];
        bv3[u] = b3[o];
#pragma unroll
        for (int k = 0; k < NBLK; k++) {
            w2[u][k] = g_w2ct[k * DIM + o];
            w3[u][k] = g_w3ct[k * DIM + o];
        }
    }

    const int b0 = blockIdx.y * FB_BCNT;

    for (int s = 0; s < FB_BCNT; s += FB_R) {
#pragma unroll
        for (int l = 0; l < 2; l++) {
            int t  = tid + 512 * l;
            int r  = t >> 8;
            int q  = t & 255;
            int k  = q >> 4;
            int cc = (q & 15) * 4;
            float4 v = *reinterpret_cast<const float4*>(
                &g_h1[(size_t)(b0 + s + r) * DIM + k * SEC + cx * 64 + cc]);
            *reinterpret_cast<float4*>(&h1s[r][k * 64 + cc]) = v;
        }
        __syncthreads();

#pragma unroll
        for (int r = 0; r < FB_R; r++) {
            float iv[NBLK];
#pragma unroll
            for (int k = 0; k < NBLK; k++) iv[k] = h1s[r][k * 64 + c];
#pragma unroll
            for (int u = 0; u < 2; u++) {
                float acc = bv2[u];
#pragma unroll
                for (int k = 0; k < NBLK; k++)
                    acc = fmaf(w2[u][k], iv[k], acc);
                h2s[r][(gq * 2 + u) * 64 + c] = fmaxf(acc, 0.0f);
            }
        }
        __syncthreads();

#pragma unroll
        for (int r = 0; r < FB_R; r++) {
            float hv[NBLK];
#pragma unroll
            for (int k = 0; k < NBLK; k++) hv[k] = h2s[r][k * 64 + c];
#pragma unroll
            for (int u = 0; u < 2; u++) {
                float acc = bv3[u];
#pragma unroll
                for (int k = 0; k < NBLK; k++)
                    acc = fmaf(w3[u][k], hv[k], acc);
                out[(size_t)(b0 + s + r) * DIM + (gq * 2 + u) * SEC + ccol] = acc;
            }
        }
        __syncthreads();
    }
}

// ---------------------------------------------------------------------------
// Launch. Inputs (metadata order): x, W1, b1, W2, b2, W3, b3, m1, m2, m3
// ---------------------------------------------------------------------------
extern "C" void kernel_launch(void* const* d_in, const int* in_sizes, int n_in,
                              void* d_out, int out_size)
{
    const float* x  = (const float*)d_in[0];
    const float* W1 = (const float*)d_in[1];
    const float* b1 = (const float*)d_in[2];
    const float* W2 = (const float*)d_in[3];
    const float* b2 = (const float*)d_in[4];
    const float* W3 = (const float*)d_in[5];
    const float* b3 = (const float*)d_in[6];
    float* out = (float*)d_out;
    (void)in_sizes; (void)n_in; (void)out_size;

    static bool attr_set = false;
    if (!attr_set) {
        cudaFuncSetAttribute(layer1_mma_kernel,
                             cudaFuncAttributeMaxDynamicSharedMemorySize,
                             SMEM_L1);
        attr_set = true;
    }

    // 1) Prep: sparse tables + bf16 hi/lo packs
    pack_kernel<<<(NBLK * DIM + 255) / 256, 256>>>(W2, W3);
    pack_w1_kernel<<<(NBLK * SEC * 64) / 256, 256>>>(W1);
    convert_x_kernel<<<(int)(((size_t)BATCH * DIM / 4) / 1024), 256>>>(x);

    // 2) Layer 1: double-buffered cp.async bf16x3 GEMM, 2 CTAs/SM
    layer1_mma_kernel<<<dim3(BATCH / 64, NBLK), 256, SMEM_L1>>>(b1);

    // 3) Layers 2+3 fused
    fused23_kernel<<<dim3(4, BATCH / FB_BCNT), 512>>>(b2, b3, out);
}

// round 13
// speedup vs baseline: 1.4548x; 1.3360x over previous
#include <cuda_runtime.h>
#include <cuda_fp16.h>
#include <cstdint>

// Problem constants
#define BATCH 4096
#define DIM   4096
#define NBLK  16
#define SEC   256

// ---------------------------------------------------------------------------
// Scratch (static device globals; no runtime allocation allowed)
// ---------------------------------------------------------------------------
__device__ float g_h1[BATCH * DIM];                 // 64 MB layer1 out
__device__ float g_w2ct[NBLK * DIM];                // compact W2
__device__ float g_w3ct[NBLK * DIM];                // compact W3
__device__ __half g_xh[(size_t)BATCH * DIM];        // 32 MB, X in fp16
__device__ __half g_wh[NBLK * SEC * SEC];           // 2 MB, W1 diag blocks fp16

__device__ __forceinline__ uint32_t smem_u32(const void* p) {
    uint32_t a;
    asm("{ .reg .u64 t; cvta.to.shared.u64 t, %1; cvt.u32.u64 %0, t; }"
        : "=r"(a) : "l"(p));
    return a;
}
__device__ __forceinline__ void cp_async16(uint32_t dst, const void* src) {
    asm volatile("cp.async.cg.shared.global [%0], [%1], 16;"
                 :: "r"(dst), "l"(src));
}
#define CP_COMMIT()  asm volatile("cp.async.commit_group;")
#define CP_WAIT(N)   asm volatile("cp.async.wait_group %0;" :: "n"(N))

// convert one float4 to 4 packed fp16 (uint2)
__device__ __forceinline__ uint2 cvt4h(const float4 v)
{
    __half2 h01 = __floats2half2_rn(v.x, v.y);
    __half2 h23 = __floats2half2_rn(v.z, v.w);
    uint2 r;
    r.x = *reinterpret_cast<uint32_t*>(&h01);
    r.y = *reinterpret_cast<uint32_t*>(&h23);
    return r;
}

__device__ __forceinline__ void ldmatrix_x4(
    uint32_t& r0, uint32_t& r1, uint32_t& r2, uint32_t& r3, uint32_t addr)
{
    asm volatile("ldmatrix.sync.aligned.m8n8.x4.shared.b16 {%0,%1,%2,%3}, [%4];"
                 : "=r"(r0), "=r"(r1), "=r"(r2), "=r"(r3) : "r"(addr));
}
__device__ __forceinline__ void mma_f16(
    float* c, uint32_t a0, uint32_t a1, uint32_t a2, uint32_t a3,
    uint32_t b0, uint32_t b1)
{
    asm volatile(
        "mma.sync.aligned.m16n8k16.row.col.f32.f16.f16.f32 "
        "{%0,%1,%2,%3}, {%4,%5,%6,%7}, {%8,%9}, {%0,%1,%2,%3};"
        : "+f"(c[0]), "+f"(c[1]), "+f"(c[2]), "+f"(c[3])
        : "r"(a0), "r"(a1), "r"(a2), "r"(a3), "r"(b0), "r"(b1));
}

// ---------------------------------------------------------------------------
// Prep kernels
// ---------------------------------------------------------------------------
__global__ void pack_kernel(const float* __restrict__ W2,
                            const float* __restrict__ W3)
{
    int idx = blockIdx.x * 256 + threadIdx.x;
    if (idx >= NBLK * DIM) return;
    int k = idx >> 12;
    int o = idx & (DIM - 1);
    int c = o & (SEC - 1);
    float v2 = (k <= (o >> 8)) ? W2[o * DIM + k * SEC + c] : 0.0f;
    g_w2ct[idx] = v2;
    g_w3ct[idx] = W3[o * DIM + k * SEC + c];
}

// X -> fp16. 4 float4 in flight per thread (MLP=4) to saturate HBM.
__global__ void __launch_bounds__(256) convert_x_kernel(const float* __restrict__ X)
{
    size_t b0 = (size_t)blockIdx.x * 1024 + threadIdx.x;
    float4 v[4];
#pragma unroll
    for (int i = 0; i < 4; i++)
        v[i] = reinterpret_cast<const float4*>(X)[b0 + i * 256];
#pragma unroll
    for (int i = 0; i < 4; i++)
        reinterpret_cast<uint2*>(g_xh)[b0 + i * 256] = cvt4h(v[i]);
}

// W1 diagonal blocks -> fp16, [z][row 0..255][k 0..255]
__global__ void __launch_bounds__(256) pack_w1_kernel(const float* __restrict__ W1)
{
    int idx = blockIdx.x * 256 + threadIdx.x;   // over 16*256*64 float4s
    int z  = idx >> 14;
    int r  = (idx >> 6) & 255;
    int c4 = idx & 63;
    float4 v = *reinterpret_cast<const float4*>(
        &W1[(size_t)(z * SEC + r) * DIM + z * SEC + c4 * 4]);
    int o = (z * SEC + r) * SEC + c4 * 4;
    *reinterpret_cast<uint2*>(&g_wh[o]) = cvt4h(v);
}

// ---------------------------------------------------------------------------
// Layer 1: single-pass fp16 GEMM, mma.sync + cp.async double buffering.
// CTA tile 64x256 (M x N): N covers a whole section -> X read exactly once.
// 256 threads = 8 warps (2m x 4n), warp tile 32x64, BK=32.
// smem per buffer: A 5120B + B 20480B = 25600B; x2 = 50KB.
// ---------------------------------------------------------------------------
#define LDS       40                     // padded row stride (fp16 elements)
#define ROWB      (LDS * 2)              // 80 bytes per row
#define SMA       0
#define SMB       (64 * ROWB)            // 5120
#define BUFSZ     (SMB + 256 * ROWB)     // 25600
#define SMEM_L1   (2 * BUFSZ)            // 51200

__device__ __forceinline__ void prefetch_chunk(
    uint32_t sbuf, int m0, int z, int k0, int tid)
{
    const int row   = tid >> 2;          // 0..63
    const int piece = tid & 3;
    // A tile: 64 rows x 32 k
    {
        size_t src = (size_t)(m0 + row) * DIM + z * SEC + k0 + piece * 8;
        cp_async16(sbuf + SMA + row * ROWB + piece * 16, &g_xh[src]);
    }
    // B tile: 256 rows x 32 k
#pragma unroll
    for (int l = 0; l < 4; l++) {
        int idx = tid + 256 * l;
        int br  = idx >> 2;
        int bp  = idx & 3;
        size_t src = (size_t)(z * SEC + br) * SEC + k0 + bp * 8;
        cp_async16(sbuf + SMB + br * ROWB + bp * 16, &g_wh[src]);
    }
}

__global__ void __launch_bounds__(256, 2) layer1_mma_kernel(
    const float* __restrict__ b1)
{
    extern __shared__ char dsm[];
    const uint32_t sbase = smem_u32(dsm);

    const int tid  = threadIdx.x;
    const int lane = tid & 31;
    const int wid  = tid >> 5;
    const int wm0  = (wid & 1) * 32;       // warp row base (0 or 32)
    const int wn0  = (wid >> 1) * 64;      // warp col base (0..192)
    const int m0   = blockIdx.x * 64;
    const int z    = blockIdx.y;

    float acc[2][8][4];
#pragma unroll
    for (int mi = 0; mi < 2; mi++)
#pragma unroll
        for (int ni = 0; ni < 8; ni++)
#pragma unroll
            for (int q = 0; q < 4; q++) acc[mi][ni][q] = 0.0f;

    // ldmatrix intra-warp offsets (bytes)
    const uint32_t a_off =
        ((lane & 15) * LDS + (lane >> 4) * 8) * 2;
    const uint32_t b_off =
        ((((lane >> 4) << 3) + (lane & 7)) * LDS + (((lane >> 3) & 1) << 3)) * 2;

    prefetch_chunk(sbase, m0, z, 0, tid);
    CP_COMMIT();

    for (int ch = 0; ch < SEC / 32; ch++) {
        if (ch + 1 < SEC / 32) {
            prefetch_chunk(sbase + ((ch + 1) & 1) * BUFSZ, m0, z, (ch + 1) * 32, tid);
            CP_COMMIT();
            CP_WAIT(1);
        } else {
            CP_WAIT(0);
        }
        __syncthreads();

        const uint32_t buf = sbase + (ch & 1) * BUFSZ;
        const uint32_t Ab  = buf + SMA;
        const uint32_t Bb  = buf + SMB;

#pragma unroll
        for (int ks = 0; ks < 2; ks++) {
            uint32_t a[2][4];
#pragma unroll
            for (int mi = 0; mi < 2; mi++) {
                uint32_t addr = Ab + a_off +
                    ((wm0 + mi * 16) * LDS + ks * 16) * 2;
                ldmatrix_x4(a[mi][0], a[mi][1], a[mi][2], a[mi][3], addr);
            }
            uint32_t b[4][4];
#pragma unroll
            for (int np = 0; np < 4; np++) {
                uint32_t addr = Bb + b_off +
                    ((wn0 + np * 16) * LDS + ks * 16) * 2;
                ldmatrix_x4(b[np][0], b[np][1], b[np][2], b[np][3], addr);
            }
#pragma unroll
            for (int mi = 0; mi < 2; mi++)
#pragma unroll
                for (int ni = 0; ni < 8; ni++) {
                    int np = ni >> 1, h = (ni & 1) * 2;
                    mma_f16(acc[mi][ni],
                            a[mi][0], a[mi][1], a[mi][2], a[mi][3],
                            b[np][h], b[np][h + 1]);
                }
        }
        __syncthreads();   // protect buffer overwrite next iteration
    }

    // ---- Epilogue: bias + ReLU, float2 stores
    const int g = lane >> 2;
    const int c = lane & 3;
#pragma unroll
    for (int mi = 0; mi < 2; mi++) {
        const int row0 = m0 + wm0 + mi * 16 + g;
        const int row1 = row0 + 8;
#pragma unroll
        for (int ni = 0; ni < 8; ni++) {
            const int col = z * SEC + wn0 + ni * 8 + 2 * c;
            const float bb0 = b1[col], bb1 = b1[col + 1];
            float2 v0, v1;
            v0.x = fmaxf(acc[mi][ni][0] + bb0, 0.0f);
            v0.y = fmaxf(acc[mi][ni][1] + bb1, 0.0f);
            v1.x = fmaxf(acc[mi][ni][2] + bb0, 0.0f);
            v1.y = fmaxf(acc[mi][ni][3] + bb1, 0.0f);
            *reinterpret_cast<float2*>(&g_h1[(size_t)row0 * DIM + col]) = v0;
            *reinterpret_cast<float2*>(&g_h1[(size_t)row1 * DIM + col]) = v1;
        }
    }
}

// ---------------------------------------------------------------------------
// FUSED layers 2+3 (unchanged): h2 lives only in shared memory.
// ---------------------------------------------------------------------------
#define FB_R    4
#define FB_BCNT 16

__global__ void __launch_bounds__(512) fused23_kernel(
    const float* __restrict__ b2,
    const float* __restrict__ b3,
    float* __restrict__ out)
{
    const int cx   = blockIdx.x;
    const int tid  = threadIdx.x;
    const int c    = tid & 63;
    const int gq   = tid >> 6;
    const int ccol = cx * 64 + c;

    __shared__ float h1s[FB_R][NBLK * 64];
    __shared__ float h2s[FB_R][NBLK * 64];

    float w2[2][NBLK], w3[2][NBLK], bv2[2], bv3[2];
#pragma unroll
    for (int u = 0; u < 2; u++) {
        int oy = gq * 2 + u;
        int o  = oy * SEC + ccol;
        bv2[u] = b2[o];
        bv3[u] = b3[o];
#pragma unroll
        for (int k = 0; k < NBLK; k++) {
            w2[u][k] = g_w2ct[k * DIM + o];
            w3[u][k] = g_w3ct[k * DIM + o];
        }
    }

    const int b0 = blockIdx.y * FB_BCNT;

    for (int s = 0; s < FB_BCNT; s += FB_R) {
#pragma unroll
        for (int l = 0; l < 2; l++) {
            int t  = tid + 512 * l;
            int r  = t >> 8;
            int q  = t & 255;
            int k  = q >> 4;
            int cc = (q & 15) * 4;
            float4 v = *reinterpret_cast<const float4*>(
                &g_h1[(size_t)(b0 + s + r) * DIM + k * SEC + cx * 64 + cc]);
            *reinterpret_cast<float4*>(&h1s[r][k * 64 + cc]) = v;
        }
        __syncthreads();

#pragma unroll
        for (int r = 0; r < FB_R; r++) {
            float iv[NBLK];
#pragma unroll
            for (int k = 0; k < NBLK; k++) iv[k] = h1s[r][k * 64 + c];
#pragma unroll
            for (int u = 0; u < 2; u++) {
                float acc = bv2[u];
#pragma unroll
                for (int k = 0; k < NBLK; k++)
                    acc = fmaf(w2[u][k], iv[k], acc);
                h2s[r][(gq * 2 + u) * 64 + c] = fmaxf(acc, 0.0f);
            }
        }
        __syncthreads();

#pragma unroll
        for (int r = 0; r < FB_R; r++) {
            float hv[NBLK];
#pragma unroll
            for (int k = 0; k < NBLK; k++) hv[k] = h2s[r][k * 64 + c];
#pragma unroll
            for (int u = 0; u < 2; u++) {
                float acc = bv3[u];
#pragma unroll
                for (int k = 0; k < NBLK; k++)
                    acc = fmaf(w3[u][k], hv[k], acc);
                out[(size_t)(b0 + s + r) * DIM + (gq * 2 + u) * SEC + ccol] = acc;
            }
        }
        __syncthreads();
    }
}

// ---------------------------------------------------------------------------
// Launch. Inputs (metadata order): x, W1, b1, W2, b2, W3, b3, m1, m2, m3
// ---------------------------------------------------------------------------
extern "C" void kernel_launch(void* const* d_in, const int* in_sizes, int n_in,
                              void* d_out, int out_size)
{
    const float* x  = (const float*)d_in[0];
    const float* W1 = (const float*)d_in[1];
    const float* b1 = (const float*)d_in[2];
    const float* W2 = (const float*)d_in[3];
    const float* b2 = (const float*)d_in[4];
    const float* W3 = (const float*)d_in[5];
    const float* b3 = (const float*)d_in[6];
    float* out = (float*)d_out;
    (void)in_sizes; (void)n_in; (void)out_size;

    static bool attr_set = false;
    if (!attr_set) {
        cudaFuncSetAttribute(layer1_mma_kernel,
                             cudaFuncAttributeMaxDynamicSharedMemorySize,
                             SMEM_L1);
        attr_set = true;
    }

    // 1) Prep: sparse tables + fp16 packs
    pack_kernel<<<(NBLK * DIM + 255) / 256, 256>>>(W2, W3);
    pack_w1_kernel<<<(NBLK * SEC * 64) / 256, 256>>>(W1);
    convert_x_kernel<<<(int)(((size_t)BATCH * DIM / 4) / 1024), 256>>>(x);

    // 2) Layer 1: double-buffered cp.async single-pass fp16 GEMM
    layer1_mma_kernel<<<dim3(BATCH / 64, NBLK), 256, SMEM_L1>>>(b1);

    // 3) Layers 2+3 fused
    fused23_kernel<<<dim3(4, BATCH / FB_BCNT), 512>>>(b2, b3, out);
}

// round 14
// speedup vs baseline: 1.6547x; 1.1374x over previous
#include <cuda_runtime.h>
#include <cuda_fp16.h>
#include <cstdint>

// Problem constants
#define BATCH 4096
#define DIM   4096
#define NBLK  16
#define SEC   256

// ---------------------------------------------------------------------------
// Scratch (static device globals; no runtime allocation allowed)
// ---------------------------------------------------------------------------
__device__ __half g_h1h[(size_t)BATCH * DIM];       // 32 MB layer1 out (fp16)
__device__ float  g_w2ct[NBLK * DIM];               // compact W2
__device__ float  g_w3ct[NBLK * DIM];               // compact W3
__device__ __half g_wh[NBLK * SEC * SEC];           // 2 MB, W1 diag blocks fp16

__device__ __forceinline__ uint32_t smem_u32(const void* p) {
    uint32_t a;
    asm("{ .reg .u64 t; cvta.to.shared.u64 t, %1; cvt.u32.u64 %0, t; }"
        : "=r"(a) : "l"(p));
    return a;
}
__device__ __forceinline__ void cp_async16(uint32_t dst, const void* src) {
    asm volatile("cp.async.cg.shared.global [%0], [%1], 16;"
                 :: "r"(dst), "l"(src));
}
#define CP_COMMIT()  asm volatile("cp.async.commit_group;")
#define CP_WAIT(N)   asm volatile("cp.async.wait_group %0;" :: "n"(N))

// convert one float4 to 4 packed fp16 (uint2)
__device__ __forceinline__ uint2 cvt4h(const float4 v)
{
    __half2 h01 = __floats2half2_rn(v.x, v.y);
    __half2 h23 = __floats2half2_rn(v.z, v.w);
    uint2 r;
    r.x = *reinterpret_cast<uint32_t*>(&h01);
    r.y = *reinterpret_cast<uint32_t*>(&h23);
    return r;
}

__device__ __forceinline__ void ldmatrix_x4(
    uint32_t& r0, uint32_t& r1, uint32_t& r2, uint32_t& r3, uint32_t addr)
{
    asm volatile("ldmatrix.sync.aligned.m8n8.x4.shared.b16 {%0,%1,%2,%3}, [%4];"
                 : "=r"(r0), "=r"(r1), "=r"(r2), "=r"(r3) : "r"(addr));
}
__device__ __forceinline__ void mma_f16(
    float* c, uint32_t a0, uint32_t a1, uint32_t a2, uint32_t a3,
    uint32_t b0, uint32_t b1)
{
    asm volatile(
        "mma.sync.aligned.m16n8k16.row.col.f32.f16.f16.f32 "
        "{%0,%1,%2,%3}, {%4,%5,%6,%7}, {%8,%9}, {%0,%1,%2,%3};"
        : "+f"(c[0]), "+f"(c[1]), "+f"(c[2]), "+f"(c[3])
        : "r"(a0), "r"(a1), "r"(a2), "r"(a3), "r"(b0), "r"(b1));
}

// ---------------------------------------------------------------------------
// Prep kernels
// ---------------------------------------------------------------------------
__global__ void pack_kernel(const float* __restrict__ W2,
                            const float* __restrict__ W3)
{
    int idx = blockIdx.x * 256 + threadIdx.x;
    if (idx >= NBLK * DIM) return;
    int k = idx >> 12;
    int o = idx & (DIM - 1);
    int c = o & (SEC - 1);
    float v2 = (k <= (o >> 8)) ? W2[o * DIM + k * SEC + c] : 0.0f;
    g_w2ct[idx] = v2;
    g_w3ct[idx] = W3[o * DIM + k * SEC + c];
}

// W1 diagonal blocks -> fp16, [z][row 0..255][k 0..255]
__global__ void __launch_bounds__(256) pack_w1_kernel(const float* __restrict__ W1)
{
    int idx = blockIdx.x * 256 + threadIdx.x;   // over 16*256*64 float4s
    int z  = idx >> 14;
    int r  = (idx >> 6) & 255;
    int c4 = idx & 63;
    float4 v = *reinterpret_cast<const float4*>(
        &W1[(size_t)(z * SEC + r) * DIM + z * SEC + c4 * 4]);
    int o = (z * SEC + r) * SEC + c4 * 4;
    *reinterpret_cast<uint2*>(&g_wh[o]) = cvt4h(v);
}

// ---------------------------------------------------------------------------
// Layer 1: fp16 GEMM, mma.sync. B via cp.async double buffering; A (X) loaded
// fp32 from global into registers one chunk ahead, converted to fp16, STS'd.
// CTA tile 64x256 (M x N), 256 threads = 8 warps (2m x 4n), warp tile 32x64,
// BK=32. h1 written as fp16. X read exactly once (fold-in of convert_x).
// ---------------------------------------------------------------------------
#define LDS       40                     // padded row stride (fp16 elements)
#define ROWB      (LDS * 2)              // 80 bytes per row
#define SMA       0
#define SMB       (64 * ROWB)            // 5120
#define BUFSZ     (SMB + 256 * ROWB)     // 25600
#define SMEM_L1   (2 * BUFSZ)            // 51200

__device__ __forceinline__ void prefetch_B(
    uint32_t sbuf, int z, int k0, int tid)
{
#pragma unroll
    for (int l = 0; l < 4; l++) {
        int idx = tid + 256 * l;
        int br  = idx >> 2;
        int bp  = idx & 3;
        size_t src = (size_t)(z * SEC + br) * SEC + k0 + bp * 8;
        cp_async16(sbuf + SMB + br * ROWB + bp * 16, &g_wh[src]);
    }
}

__device__ __forceinline__ void load_A_regs(
    float4* a_pre, const float* __restrict__ X, int m0, int z, int k0, int tid)
{
    const int row   = tid >> 2;          // 0..63
    const int piece = tid & 3;           // 8 floats each
    const float* src = &X[(size_t)(m0 + row) * DIM + z * SEC + k0 + piece * 8];
    a_pre[0] = *reinterpret_cast<const float4*>(src);
    a_pre[1] = *reinterpret_cast<const float4*>(src + 4);
}

__global__ void __launch_bounds__(256, 2) layer1_mma_kernel(
    const float* __restrict__ X,
    const float* __restrict__ b1)
{
    extern __shared__ char dsm[];
    const uint32_t sbase = smem_u32(dsm);

    const int tid  = threadIdx.x;
    const int lane = tid & 31;
    const int wid  = tid >> 5;
    const int wm0  = (wid & 1) * 32;       // warp row base (0 or 32)
    const int wn0  = (wid >> 1) * 64;      // warp col base (0..192)
    const int m0   = blockIdx.x * 64;
    const int z    = blockIdx.y;

    // A sts address (same mapping as cp_async16 path; 16B aligned)
    const uint32_t a_sts = sbase + SMA + (tid >> 2) * ROWB + (tid & 3) * 16;

    float acc[2][8][4];
#pragma unroll
    for (int mi = 0; mi < 2; mi++)
#pragma unroll
        for (int ni = 0; ni < 8; ni++)
#pragma unroll
            for (int q = 0; q < 4; q++) acc[mi][ni][q] = 0.0f;

    // ldmatrix intra-warp offsets (bytes)
    const uint32_t a_off =
        ((lane & 15) * LDS + (lane >> 4) * 8) * 2;
    const uint32_t b_off =
        ((((lane >> 4) << 3) + (lane & 7)) * LDS + (((lane >> 3) & 1) << 3)) * 2;

    // Prologue: A(0) into regs, B(0) via cp.async
    float4 a_pre[2];
    load_A_regs(a_pre, X, m0, z, 0, tid);
    prefetch_B(sbase, z, 0, tid);
    CP_COMMIT();

    for (int ch = 0; ch < SEC / 32; ch++) {
        const uint32_t buf = sbase + (ch & 1) * BUFSZ;

        // stage A(ch) regs -> smem (fp16)
        uint4 ah;
        {
            uint2 h0 = cvt4h(a_pre[0]);
            uint2 h1 = cvt4h(a_pre[1]);
            ah.x = h0.x; ah.y = h0.y; ah.z = h1.x; ah.w = h1.y;
        }
        *reinterpret_cast<uint4*>(
            reinterpret_cast<char*>(dsm) + (buf - sbase) + (a_sts - sbase - SMA)) = ah;

        // prefetch next chunk
        if (ch + 1 < SEC / 32) {
            load_A_regs(a_pre, X, m0, z, (ch + 1) * 32, tid);
            prefetch_B(sbase + ((ch + 1) & 1) * BUFSZ, z, (ch + 1) * 32, tid);
            CP_COMMIT();
            CP_WAIT(1);
        } else {
            CP_WAIT(0);
        }
        __syncthreads();   // A sts + B cp.async visible to all warps

        const uint32_t Ab = buf + SMA;
        const uint32_t Bb = buf + SMB;

#pragma unroll
        for (int ks = 0; ks < 2; ks++) {
            uint32_t a[2][4];
#pragma unroll
            for (int mi = 0; mi < 2; mi++) {
                uint32_t addr = Ab + a_off +
                    ((wm0 + mi * 16) * LDS + ks * 16) * 2;
                ldmatrix_x4(a[mi][0], a[mi][1], a[mi][2], a[mi][3], addr);
            }
            uint32_t b[4][4];
#pragma unroll
            for (int np = 0; np < 4; np++) {
                uint32_t addr = Bb + b_off +
                    ((wn0 + np * 16) * LDS + ks * 16) * 2;
                ldmatrix_x4(b[np][0], b[np][1], b[np][2], b[np][3], addr);
            }
#pragma unroll
            for (int mi = 0; mi < 2; mi++)
#pragma unroll
                for (int ni = 0; ni < 8; ni++) {
                    int np = ni >> 1, h = (ni & 1) * 2;
                    mma_f16(acc[mi][ni],
                            a[mi][0], a[mi][1], a[mi][2], a[mi][3],
                            b[np][h], b[np][h + 1]);
                }
        }
        __syncthreads();   // protect buffer overwrite next iteration
    }

    // ---- Epilogue: bias + ReLU, fp16 stores (half2 per acc pair)
    const int g = lane >> 2;
    const int c = lane & 3;
#pragma unroll
    for (int mi = 0; mi < 2; mi++) {
        const int row0 = m0 + wm0 + mi * 16 + g;
        const int row1 = row0 + 8;
#pragma unroll
        for (int ni = 0; ni < 8; ni++) {
            const int col = z * SEC + wn0 + ni * 8 + 2 * c;
            const float bb0 = b1[col], bb1 = b1[col + 1];
            __half2 v0 = __floats2half2_rn(
                fmaxf(acc[mi][ni][0] + bb0, 0.0f),
                fmaxf(acc[mi][ni][1] + bb1, 0.0f));
            __half2 v1 = __floats2half2_rn(
                fmaxf(acc[mi][ni][2] + bb0, 0.0f),
                fmaxf(acc[mi][ni][3] + bb1, 0.0f));
            *reinterpret_cast<__half2*>(&g_h1h[(size_t)row0 * DIM + col]) = v0;
            *reinterpret_cast<__half2*>(&g_h1h[(size_t)row1 * DIM + col]) = v1;
        }
    }
}

// ---------------------------------------------------------------------------
// FUSED layers 2+3: h2 lives only in shared memory; h1 read as fp16.
// ---------------------------------------------------------------------------
#define FB_R    4
#define FB_BCNT 16

__global__ void __launch_bounds__(512) fused23_kernel(
    const float* __restrict__ b2,
    const float* __restrict__ b3,
    float* __restrict__ out)
{
    const int cx   = blockIdx.x;
    const int tid  = threadIdx.x;
    const int c    = tid & 63;
    const int gq   = tid >> 6;
    const int ccol = cx * 64 + c;

    __shared__ float h1s[FB_R][NBLK * 64];
    __shared__ float h2s[FB_R][NBLK * 64];

    float w2[2][NBLK], w3[2][NBLK], bv2[2], bv3[2];
#pragma unroll
    for (int u = 0; u < 2; u++) {
        int oy = gq * 2 + u;
        int o  = oy * SEC + ccol;
        bv2[u] = b2[o];
        bv3[u] = b3[o];
#pragma unroll
        for (int k = 0; k < NBLK; k++) {
            w2[u][k] = g_w2ct[k * DIM + o];
            w3[u][k] = g_w3ct[k * DIM + o];
        }
    }

    const int b0 = blockIdx.y * FB_BCNT;

    for (int s = 0; s < FB_BCNT; s += FB_R) {
        // load FB_R rows x (16 k x 64 c) fp16 slab: 512 threads x 8 halves
        {
            int r  = tid >> 7;               // 0..3
            int q  = tid & 127;              // 0..127
            int k  = q >> 3;                 // 0..15
            int c8 = (q & 7) * 8;            // 0..56
            uint4 raw = *reinterpret_cast<const uint4*>(
                &g_h1h[(size_t)(b0 + s + r) * DIM + k * SEC + cx * 64 + c8]);
            const __half2* hp = reinterpret_cast<const __half2*>(&raw);
            float* dst = &h1s[r][k * 64 + c8];
#pragma unroll
            for (int i = 0; i < 4; i++) {
                float2 f = __half22float2(hp[i]);
                dst[i * 2 + 0] = f.x;
                dst[i * 2 + 1] = f.y;
            }
        }
        __syncthreads();

#pragma unroll
        for (int r = 0; r < FB_R; r++) {
            float iv[NBLK];
#pragma unroll
            for (int k = 0; k < NBLK; k++) iv[k] = h1s[r][k * 64 + c];
#pragma unroll
            for (int u = 0; u < 2; u++) {
                float acc = bv2[u];
#pragma unroll
                for (int k = 0; k < NBLK; k++)
                    acc = fmaf(w2[u][k], iv[k], acc);
                h2s[r][(gq * 2 + u) * 64 + c] = fmaxf(acc, 0.0f);
            }
        }
        __syncthreads();

#pragma unroll
        for (int r = 0; r < FB_R; r++) {
            float hv[NBLK];
#pragma unroll
            for (int k = 0; k < NBLK; k++) hv[k] = h2s[r][k * 64 + c];
#pragma unroll
            for (int u = 0; u < 2; u++) {
                float acc = bv3[u];
#pragma unroll
                for (int k = 0; k < NBLK; k++)
                    acc = fmaf(w3[u][k], hv[k], acc);
                out[(size_t)(b0 + s + r) * DIM + (gq * 2 + u) * SEC + ccol] = acc;
            }
        }
        __syncthreads();
    }
}

// ---------------------------------------------------------------------------
// Launch. Inputs (metadata order): x, W1, b1, W2, b2, W3, b3, m1, m2, m3
// ---------------------------------------------------------------------------
extern "C" void kernel_launch(void* const* d_in, const int* in_sizes, int n_in,
                              void* d_out, int out_size)
{
    const float* x  = (const float*)d_in[0];
    const float* W1 = (const float*)d_in[1];
    const float* b1 = (const float*)d_in[2];
    const float* W2 = (const float*)d_in[3];
    const float* b2 = (const float*)d_in[4];
    const float* W3 = (const float*)d_in[5];
    const float* b3 = (const float*)d_in[6];
    float* out = (float*)d_out;
    (void)in_sizes; (void)n_in; (void)out_size;

    static bool attr_set = false;
    if (!attr_set) {
        cudaFuncSetAttribute(layer1_mma_kernel,
                             cudaFuncAttributeMaxDynamicSharedMemorySize,
                             SMEM_L1);
        attr_set = true;
    }

    // 1) Prep: sparse tables + fp16 weight pack (X converted inside layer1)
    pack_kernel<<<(NBLK * DIM + 255) / 256, 256>>>(W2, W3);
    pack_w1_kernel<<<(NBLK * SEC * 64) / 256, 256>>>(W1);

    // 2) Layer 1: fp16 GEMM, A from fp32 X (register-staged), B via cp.async
    layer1_mma_kernel<<<dim3(BATCH / 64, NBLK), 256, SMEM_L1>>>(x, b1);

    // 3) Layers 2+3 fused (h1 fp16 -> fp32 in registers)
    fused23_kernel<<<dim3(4, BATCH / FB_BCNT), 512>>>(b2, b3, out);
}

// round 15
// speedup vs baseline: 1.9457x; 1.1759x over previous
#include <cuda_runtime.h>
#include <cuda_fp16.h>
#include <cstdint>

// Problem constants
#define BATCH 4096
#define DIM   4096
#define NBLK  16
#define SEC   256

// ---------------------------------------------------------------------------
// Scratch (static device globals; no runtime allocation allowed)
// ---------------------------------------------------------------------------
__device__ __half g_h1h[(size_t)BATCH * DIM];       // 32 MB layer1 out (fp16)
__device__ float  g_w2ct[NBLK * DIM];               // compact W2
__device__ float  g_w3ct[NBLK * DIM];               // compact W3
__device__ __half g_wh[NBLK * SEC * SEC];           // 2 MB, W1 diag blocks fp16

__device__ __forceinline__ uint32_t smem_u32(const void* p) {
    uint32_t a;
    asm("{ .reg .u64 t; cvta.to.shared.u64 t, %1; cvt.u32.u64 %0, t; }"
        : "=r"(a) : "l"(p));
    return a;
}
__device__ __forceinline__ void cp_async16(uint32_t dst, const void* src) {
    asm volatile("cp.async.cg.shared.global [%0], [%1], 16;"
                 :: "r"(dst), "l"(src));
}
#define CP_COMMIT()  asm volatile("cp.async.commit_group;")
#define CP_WAIT(N)   asm volatile("cp.async.wait_group %0;" :: "n"(N))

// convert one float4 to 4 packed fp16 (uint2)
__device__ __forceinline__ uint2 cvt4h(const float4 v)
{
    __half2 h01 = __floats2half2_rn(v.x, v.y);
    __half2 h23 = __floats2half2_rn(v.z, v.w);
    uint2 r;
    r.x = *reinterpret_cast<uint32_t*>(&h01);
    r.y = *reinterpret_cast<uint32_t*>(&h23);
    return r;
}

__device__ __forceinline__ void ldmatrix_x4(
    uint32_t& r0, uint32_t& r1, uint32_t& r2, uint32_t& r3, uint32_t addr)
{
    asm volatile("ldmatrix.sync.aligned.m8n8.x4.shared.b16 {%0,%1,%2,%3}, [%4];"
                 : "=r"(r0), "=r"(r1), "=r"(r2), "=r"(r3) : "r"(addr));
}
__device__ __forceinline__ void mma_f16(
    float* c, uint32_t a0, uint32_t a1, uint32_t a2, uint32_t a3,
    uint32_t b0, uint32_t b1)
{
    asm volatile(
        "mma.sync.aligned.m16n8k16.row.col.f32.f16.f16.f32 "
        "{%0,%1,%2,%3}, {%4,%5,%6,%7}, {%8,%9}, {%0,%1,%2,%3};"
        : "+f"(c[0]), "+f"(c[1]), "+f"(c[2]), "+f"(c[3])
        : "r"(a0), "r"(a1), "r"(a2), "r"(a3), "r"(b0), "r"(b1));
}

// ---------------------------------------------------------------------------
// Prep kernels
// ---------------------------------------------------------------------------
__global__ void pack_kernel(const float* __restrict__ W2,
                            const float* __restrict__ W3)
{
    int idx = blockIdx.x * 256 + threadIdx.x;
    if (idx >= NBLK * DIM) return;
    int k = idx >> 12;
    int o = idx & (DIM - 1);
    int c = o & (SEC - 1);
    float v2 = (k <= (o >> 8)) ? W2[o * DIM + k * SEC + c] : 0.0f;
    g_w2ct[idx] = v2;
    g_w3ct[idx] = W3[o * DIM + k * SEC + c];
}

// W1 diagonal blocks -> fp16, [z][row 0..255][k 0..255]
__global__ void __launch_bounds__(256) pack_w1_kernel(const float* __restrict__ W1)
{
    int idx = blockIdx.x * 256 + threadIdx.x;   // over 16*256*64 float4s
    int z  = idx >> 14;
    int r  = (idx >> 6) & 255;
    int c4 = idx & 63;
    float4 v = *reinterpret_cast<const float4*>(
        &W1[(size_t)(z * SEC + r) * DIM + z * SEC + c4 * 4]);
    int o = (z * SEC + r) * SEC + c4 * 4;
    *reinterpret_cast<uint2*>(&g_wh[o]) = cvt4h(v);
}

// ---------------------------------------------------------------------------
// Layer 1 (unchanged from R14): fp16 GEMM, mma.sync. B via cp.async double
// buffering; A (X) loaded fp32 into registers one chunk ahead, cvt, STS.
// CTA tile 64x256, 256 threads = 8 warps (2m x 4n), warp tile 32x64, BK=32.
// ---------------------------------------------------------------------------
#define LDS       40                     // padded row stride (fp16 elements)
#define ROWB      (LDS * 2)              // 80 bytes per row
#define SMA       0
#define SMB       (64 * ROWB)            // 5120
#define BUFSZ     (SMB + 256 * ROWB)     // 25600
#define SMEM_L1   (2 * BUFSZ)            // 51200

__device__ __forceinline__ void prefetch_B(
    uint32_t sbuf, int z, int k0, int tid)
{
#pragma unroll
    for (int l = 0; l < 4; l++) {
        int idx = tid + 256 * l;
        int br  = idx >> 2;
        int bp  = idx & 3;
        size_t src = (size_t)(z * SEC + br) * SEC + k0 + bp * 8;
        cp_async16(sbuf + SMB + br * ROWB + bp * 16, &g_wh[src]);
    }
}

__device__ __forceinline__ void load_A_regs(
    float4* a_pre, const float* __restrict__ X, int m0, int z, int k0, int tid)
{
    const int row   = tid >> 2;          // 0..63
    const int piece = tid & 3;           // 8 floats each
    const float* src = &X[(size_t)(m0 + row) * DIM + z * SEC + k0 + piece * 8];
    a_pre[0] = *reinterpret_cast<const float4*>(src);
    a_pre[1] = *reinterpret_cast<const float4*>(src + 4);
}

__global__ void __launch_bounds__(256, 2) layer1_mma_kernel(
    const float* __restrict__ X,
    const float* __restrict__ b1)
{
    extern __shared__ char dsm[];
    const uint32_t sbase = smem_u32(dsm);

    const int tid  = threadIdx.x;
    const int lane = tid & 31;
    const int wid  = tid >> 5;
    const int wm0  = (wid & 1) * 32;
    const int wn0  = (wid >> 1) * 64;
    const int m0   = blockIdx.x * 64;
    const int z    = blockIdx.y;

    const uint32_t a_sts = sbase + SMA + (tid >> 2) * ROWB + (tid & 3) * 16;

    float acc[2][8][4];
#pragma unroll
    for (int mi = 0; mi < 2; mi++)
#pragma unroll
        for (int ni = 0; ni < 8; ni++)
#pragma unroll
            for (int q = 0; q < 4; q++) acc[mi][ni][q] = 0.0f;

    const uint32_t a_off =
        ((lane & 15) * LDS + (lane >> 4) * 8) * 2;
    const uint32_t b_off =
        ((((lane >> 4) << 3) + (lane & 7)) * LDS + (((lane >> 3) & 1) << 3)) * 2;

    float4 a_pre[2];
    load_A_regs(a_pre, X, m0, z, 0, tid);
    prefetch_B(sbase, z, 0, tid);
    CP_COMMIT();

    for (int ch = 0; ch < SEC / 32; ch++) {
        const uint32_t buf = sbase + (ch & 1) * BUFSZ;

        uint4 ah;
        {
            uint2 h0 = cvt4h(a_pre[0]);
            uint2 h1 = cvt4h(a_pre[1]);
            ah.x = h0.x; ah.y = h0.y; ah.z = h1.x; ah.w = h1.y;
        }
        *reinterpret_cast<uint4*>(
            reinterpret_cast<char*>(dsm) + (buf - sbase) + (a_sts - sbase - SMA)) = ah;

        if (ch + 1 < SEC / 32) {
            load_A_regs(a_pre, X, m0, z, (ch + 1) * 32, tid);
            prefetch_B(sbase + ((ch + 1) & 1) * BUFSZ, z, (ch + 1) * 32, tid);
            CP_COMMIT();
            CP_WAIT(1);
        } else {
            CP_WAIT(0);
        }
        __syncthreads();

        const uint32_t Ab = buf + SMA;
        const uint32_t Bb = buf + SMB;

#pragma unroll
        for (int ks = 0; ks < 2; ks++) {
            uint32_t a[2][4];
#pragma unroll
            for (int mi = 0; mi < 2; mi++) {
                uint32_t addr = Ab + a_off +
                    ((wm0 + mi * 16) * LDS + ks * 16) * 2;
                ldmatrix_x4(a[mi][0], a[mi][1], a[mi][2], a[mi][3], addr);
            }
            uint32_t b[4][4];
#pragma unroll
            for (int np = 0; np < 4; np++) {
                uint32_t addr = Bb + b_off +
                    ((wn0 + np * 16) * LDS + ks * 16) * 2;
                ldmatrix_x4(b[np][0], b[np][1], b[np][2], b[np][3], addr);
            }
#pragma unroll
            for (int mi = 0; mi < 2; mi++)
#pragma unroll
                for (int ni = 0; ni < 8; ni++) {
                    int np = ni >> 1, h = (ni & 1) * 2;
                    mma_f16(acc[mi][ni],
                            a[mi][0], a[mi][1], a[mi][2], a[mi][3],
                            b[np][h], b[np][h + 1]);
                }
        }
        __syncthreads();
    }

    const int g = lane >> 2;
    const int c = lane & 3;
#pragma unroll
    for (int mi = 0; mi < 2; mi++) {
        const int row0 = m0 + wm0 + mi * 16 + g;
        const int row1 = row0 + 8;
#pragma unroll
        for (int ni = 0; ni < 8; ni++) {
            const int col = z * SEC + wn0 + ni * 8 + 2 * c;
            const float bb0 = b1[col], bb1 = b1[col + 1];
            __half2 v0 = __floats2half2_rn(
                fmaxf(acc[mi][ni][0] + bb0, 0.0f),
                fmaxf(acc[mi][ni][1] + bb1, 0.0f));
            __half2 v1 = __floats2half2_rn(
                fmaxf(acc[mi][ni][2] + bb0, 0.0f),
                fmaxf(acc[mi][ni][3] + bb1, 0.0f));
            *reinterpret_cast<__half2*>(&g_h1h[(size_t)row0 * DIM + col]) = v0;
            *reinterpret_cast<__half2*>(&g_h1h[(size_t)row1 * DIM + col]) = v1;
        }
    }
}

// ---------------------------------------------------------------------------
// FUSED layers 2+3, v2: 256 threads (32 c-cols x 8 warp-groups, 2 o-blocks
// per thread), 2 CTAs/SM, FB_R=8 rows per 2 barriers, vectorized fp16 slab
// staging with LDG prefetch overlapped into layer-2 compute.
// ---------------------------------------------------------------------------
#define FB_R    8
#define FB_BCNT 32

__global__ void __launch_bounds__(256, 2) fused23_kernel(
    const float* __restrict__ b2,
    const float* __restrict__ b3,
    float* __restrict__ out)
{
    const int cx   = blockIdx.x;              // 0..7
    const int tid  = threadIdx.x;
    const int c    = tid & 31;
    const int gq   = tid >> 5;                // 0..7 (warp id)
    const int ccol = cx * 32 + c;             // 0..255

    __shared__ float h1s[FB_R][NBLK * 32];    // 16 KB
    __shared__ float h2s[FB_R][NBLK * 32];    // 16 KB

    // Weights + biases in registers (coalesced: lanes have consecutive c)
    float w2[2][NBLK], w3[2][NBLK], bv2[2], bv3[2];
#pragma unroll
    for (int u = 0; u < 2; u++) {
        int o  = (gq * 2 + u) * SEC + ccol;
        bv2[u] = b2[o];
        bv3[u] = b3[o];
#pragma unroll
        for (int k = 0; k < NBLK; k++) {
            w2[u][k] = g_w2ct[k * DIM + o];
            w3[u][k] = g_w3ct[k * DIM + o];
        }
    }

    const int b0 = blockIdx.y * FB_BCNT;

    // slab staging map: 8 rows x 16k x 32c halves; thread holds 2 uint4
    const int sk  = (tid & 63) >> 2;          // 0..15
    const int sc8 = (tid & 3) * 8;            // 0,8,16,24
    const int sr  = tid >> 6;                 // 0..3 (also sr+4)

    uint4 slab[2];
#pragma unroll
    for (int i = 0; i < 2; i++)
        slab[i] = *reinterpret_cast<const uint4*>(
            &g_h1h[(size_t)(b0 + sr + 4 * i) * DIM + sk * SEC + cx * 32 + sc8]);

    for (int s = 0; s < FB_BCNT; s += FB_R) {
        // ---- stage slab regs -> h1s (fp32), vectorized
#pragma unroll
        for (int i = 0; i < 2; i++) {
            const __half2* hp = reinterpret_cast<const __half2*>(&slab[i]);
            float2 f0 = __half22float2(hp[0]);
            float2 f1 = __half22float2(hp[1]);
            float2 f2 = __half22float2(hp[2]);
            float2 f3 = __half22float2(hp[3]);
            float4 lo = make_float4(f0.x, f0.y, f1.x, f1.y);
            float4 hi = make_float4(f2.x, f2.y, f3.x, f3.y);
            *reinterpret_cast<float4*>(&h1s[sr + 4 * i][sk * 32 + sc8])     = lo;
            *reinterpret_cast<float4*>(&h1s[sr + 4 * i][sk * 32 + sc8 + 4]) = hi;
        }
        __syncthreads();                       // (1) h1s ready; h2s free

        // prefetch next slab (overlaps with layer-2 compute)
        if (s + FB_R < FB_BCNT) {
#pragma unroll
            for (int i = 0; i < 2; i++)
                slab[i] = *reinterpret_cast<const uint4*>(
                    &g_h1h[(size_t)(b0 + s + FB_R + sr + 4 * i) * DIM +
                           sk * SEC + cx * 32 + sc8]);
        }

        // ---- layer 2: 2 outputs per thread per row
#pragma unroll
        for (int r = 0; r < FB_R; r++) {
            float iv[NBLK];
#pragma unroll
            for (int k = 0; k < NBLK; k++) iv[k] = h1s[r][k * 32 + c];
#pragma unroll
            for (int u = 0; u < 2; u++) {
                float acc = bv2[u];
#pragma unroll
                for (int k = 0; k < NBLK; k++)
                    acc = fmaf(w2[u][k], iv[k], acc);
                h2s[r][(gq * 2 + u) * 32 + c] = fmaxf(acc, 0.0f);
            }
        }
        __syncthreads();                       // (2) h2s ready; h1s free

        // ---- layer 3: 2 outputs per thread per row, direct STG
#pragma unroll
        for (int r = 0; r < FB_R; r++) {
            float hv[NBLK];
#pragma unroll
            for (int k = 0; k < NBLK; k++) hv[k] = h2s[r][k * 32 + c];
#pragma unroll
            for (int u = 0; u < 2; u++) {
                float acc = bv3[u];
#pragma unroll
                for (int k = 0; k < NBLK; k++)
                    acc = fmaf(w3[u][k], hv[k], acc);
                out[(size_t)(b0 + s + r) * DIM + (gq * 2 + u) * SEC + ccol] = acc;
            }
        }
        // no barrier: next STS (h1s) races nothing (h1s unread in L3),
        // and barrier (1) orders it before the next L2 reads.
    }
}

// ---------------------------------------------------------------------------
// Launch. Inputs (metadata order): x, W1, b1, W2, b2, W3, b3, m1, m2, m3
// ---------------------------------------------------------------------------
extern "C" void kernel_launch(void* const* d_in, const int* in_sizes, int n_in,
                              void* d_out, int out_size)
{
    const float* x  = (const float*)d_in[0];
    const float* W1 = (const float*)d_in[1];
    const float* b1 = (const float*)d_in[2];
    const float* W2 = (const float*)d_in[3];
    const float* b2 = (const float*)d_in[4];
    const float* W3 = (const float*)d_in[5];
    const float* b3 = (const float*)d_in[6];
    float* out = (float*)d_out;
    (void)in_sizes; (void)n_in; (void)out_size;

    static bool attr_set = false;
    if (!attr_set) {
        cudaFuncSetAttribute(layer1_mma_kernel,
                             cudaFuncAttributeMaxDynamicSharedMemorySize,
                             SMEM_L1);
        attr_set = true;
    }

    // 1) Prep: sparse tables + fp16 weight pack (X converted inside layer1)
    pack_kernel<<<(NBLK * DIM + 255) / 256, 256>>>(W2, W3);
    pack_w1_kernel<<<(NBLK * SEC * 64) / 256, 256>>>(W1);

    // 2) Layer 1: fp16 GEMM, A from fp32 X (register-staged), B via cp.async
    layer1_mma_kernel<<<dim3(BATCH / 64, NBLK), 256, SMEM_L1>>>(x, b1);

    // 3) Layers 2+3 fused, v2 (2 CTAs/SM, 2 barriers per 8 rows)
    fused23_kernel<<<dim3(8, BATCH / FB_BCNT), 256>>>(b2, b3, out);
}

// round 16
// speedup vs baseline: 1.9997x; 1.0277x over previous
#include <cuda_runtime.h>
#include <cuda_fp16.h>
#include <cstdint>

// Problem constants
#define BATCH 4096
#define DIM   4096
#define NBLK  16
#define SEC   256

// ---------------------------------------------------------------------------
// Scratch (static device globals; no runtime allocation allowed)
// ---------------------------------------------------------------------------
__device__ __half g_h1h[(size_t)BATCH * DIM];       // 32 MB layer1 out (fp16)
__device__ float  g_w2ct[NBLK * DIM];               // compact W2
__device__ float  g_w3ct[NBLK * DIM];               // compact W3
__device__ __half g_wh[NBLK * SEC * SEC];           // 2 MB, W1 diag blocks fp16

__device__ __forceinline__ uint32_t smem_u32(const void* p) {
    uint32_t a;
    asm("{ .reg .u64 t; cvta.to.shared.u64 t, %1; cvt.u32.u64 %0, t; }"
        : "=r"(a) : "l"(p));
    return a;
}
__device__ __forceinline__ void cp_async16(uint32_t dst, const void* src) {
    asm volatile("cp.async.cg.shared.global [%0], [%1], 16;"
                 :: "r"(dst), "l"(src));
}
#define CP_COMMIT()  asm volatile("cp.async.commit_group;")
#define CP_WAIT(N)   asm volatile("cp.async.wait_group %0;" :: "n"(N))

// convert one float4 to 4 packed fp16 (uint2)
__device__ __forceinline__ uint2 cvt4h(const float4 v)
{
    __half2 h01 = __floats2half2_rn(v.x, v.y);
    __half2 h23 = __floats2half2_rn(v.z, v.w);
    uint2 r;
    r.x = *reinterpret_cast<uint32_t*>(&h01);
    r.y = *reinterpret_cast<uint32_t*>(&h23);
    return r;
}

__device__ __forceinline__ void ldmatrix_x4(
    uint32_t& r0, uint32_t& r1, uint32_t& r2, uint32_t& r3, uint32_t addr)
{
    asm volatile("ldmatrix.sync.aligned.m8n8.x4.shared.b16 {%0,%1,%2,%3}, [%4];"
                 : "=r"(r0), "=r"(r1), "=r"(r2), "=r"(r3) : "r"(addr));
}
__device__ __forceinline__ void mma_f16(
    float* c, uint32_t a0, uint32_t a1, uint32_t a2, uint32_t a3,
    uint32_t b0, uint32_t b1)
{
    asm volatile(
        "mma.sync.aligned.m16n8k16.row.col.f32.f16.f16.f32 "
        "{%0,%1,%2,%3}, {%4,%5,%6,%7}, {%8,%9}, {%0,%1,%2,%3};"
        : "+f"(c[0]), "+f"(c[1]), "+f"(c[2]), "+f"(c[3])
        : "r"(a0), "r"(a1), "r"(a2), "r"(a3), "r"(b0), "r"(b1));
}

// ---------------------------------------------------------------------------
// Prep kernels
// ---------------------------------------------------------------------------
__global__ void __launch_bounds__(256) pack_kernel(const float* __restrict__ W2,
                                                   const float* __restrict__ W3)
{
    int t = blockIdx.x * 256 + threadIdx.x;     // 16K threads, 4 items each
#pragma unroll
    for (int i = 0; i < 4; i++) {
        int idx = t + i * 16384;
        int k = idx >> 12;
        int o = idx & (DIM - 1);
        int c = o & (SEC - 1);
        float v2 = (k <= (o >> 8)) ? W2[o * DIM + k * SEC + c] : 0.0f;
        g_w2ct[idx] = v2;
        g_w3ct[idx] = W3[o * DIM + k * SEC + c];
    }
}

// W1 diagonal blocks -> fp16, [z][row 0..255][k 0..255]
__global__ void __launch_bounds__(256) pack_w1_kernel(const float* __restrict__ W1)
{
    int idx = blockIdx.x * 256 + threadIdx.x;   // over 16*256*64 float4s
    int z  = idx >> 14;
    int r  = (idx >> 6) & 255;
    int c4 = idx & 63;
    float4 v = *reinterpret_cast<const float4*>(
        &W1[(size_t)(z * SEC + r) * DIM + z * SEC + c4 * 4]);
    int o = (z * SEC + r) * SEC + c4 * 4;
    *reinterpret_cast<uint2*>(&g_wh[o]) = cvt4h(v);
}

// ---------------------------------------------------------------------------
// Layer 1 (unchanged, passed twice): fp16 GEMM, mma.sync. B via cp.async
// double buffering; A (X) fp32 -> regs one chunk ahead, cvt, STS.
// CTA tile 64x256, 256 threads = 8 warps (2m x 4n), warp tile 32x64, BK=32.
// ---------------------------------------------------------------------------
#define LDS       40
#define ROWB      (LDS * 2)
#define SMA       0
#define SMB       (64 * ROWB)
#define BUFSZ     (SMB + 256 * ROWB)
#define SMEM_L1   (2 * BUFSZ)

__device__ __forceinline__ void prefetch_B(
    uint32_t sbuf, int z, int k0, int tid)
{
#pragma unroll
    for (int l = 0; l < 4; l++) {
        int idx = tid + 256 * l;
        int br  = idx >> 2;
        int bp  = idx & 3;
        size_t src = (size_t)(z * SEC + br) * SEC + k0 + bp * 8;
        cp_async16(sbuf + SMB + br * ROWB + bp * 16, &g_wh[src]);
    }
}

__device__ __forceinline__ void load_A_regs(
    float4* a_pre, const float* __restrict__ X, int m0, int z, int k0, int tid)
{
    const int row   = tid >> 2;
    const int piece = tid & 3;
    const float* src = &X[(size_t)(m0 + row) * DIM + z * SEC + k0 + piece * 8];
    a_pre[0] = *reinterpret_cast<const float4*>(src);
    a_pre[1] = *reinterpret_cast<const float4*>(src + 4);
}

__global__ void __launch_bounds__(256, 2) layer1_mma_kernel(
    const float* __restrict__ X,
    const float* __restrict__ b1)
{
    extern __shared__ char dsm[];
    const uint32_t sbase = smem_u32(dsm);

    const int tid  = threadIdx.x;
    const int lane = tid & 31;
    const int wid  = tid >> 5;
    const int wm0  = (wid & 1) * 32;
    const int wn0  = (wid >> 1) * 64;
    const int m0   = blockIdx.x * 64;
    const int z    = blockIdx.y;

    const uint32_t a_sts = sbase + SMA + (tid >> 2) * ROWB + (tid & 3) * 16;

    float acc[2][8][4];
#pragma unroll
    for (int mi = 0; mi < 2; mi++)
#pragma unroll
        for (int ni = 0; ni < 8; ni++)
#pragma unroll
            for (int q = 0; q < 4; q++) acc[mi][ni][q] = 0.0f;

    const uint32_t a_off =
        ((lane & 15) * LDS + (lane >> 4) * 8) * 2;
    const uint32_t b_off =
        ((((lane >> 4) << 3) + (lane & 7)) * LDS + (((lane >> 3) & 1) << 3)) * 2;

    float4 a_pre[2];
    load_A_regs(a_pre, X, m0, z, 0, tid);
    prefetch_B(sbase, z, 0, tid);
    CP_COMMIT();

    for (int ch = 0; ch < SEC / 32; ch++) {
        const uint32_t buf = sbase + (ch & 1) * BUFSZ;

        uint4 ah;
        {
            uint2 h0 = cvt4h(a_pre[0]);
            uint2 h1 = cvt4h(a_pre[1]);
            ah.x = h0.x; ah.y = h0.y; ah.z = h1.x; ah.w = h1.y;
        }
        *reinterpret_cast<uint4*>(
            reinterpret_cast<char*>(dsm) + (buf - sbase) + (a_sts - sbase - SMA)) = ah;

        if (ch + 1 < SEC / 32) {
            load_A_regs(a_pre, X, m0, z, (ch + 1) * 32, tid);
            prefetch_B(sbase + ((ch + 1) & 1) * BUFSZ, z, (ch + 1) * 32, tid);
            CP_COMMIT();
            CP_WAIT(1);
        } else {
            CP_WAIT(0);
        }
        __syncthreads();

        const uint32_t Ab = buf + SMA;
        const uint32_t Bb = buf + SMB;

#pragma unroll
        for (int ks = 0; ks < 2; ks++) {
            uint32_t a[2][4];
#pragma unroll
            for (int mi = 0; mi < 2; mi++) {
                uint32_t addr = Ab + a_off +
                    ((wm0 + mi * 16) * LDS + ks * 16) * 2;
                ldmatrix_x4(a[mi][0], a[mi][1], a[mi][2], a[mi][3], addr);
            }
            uint32_t b[4][4];
#pragma unroll
            for (int np = 0; np < 4; np++) {
                uint32_t addr = Bb + b_off +
                    ((wn0 + np * 16) * LDS + ks * 16) * 2;
                ldmatrix_x4(b[np][0], b[np][1], b[np][2], b[np][3], addr);
            }
#pragma unroll
            for (int mi = 0; mi < 2; mi++)
#pragma unroll
                for (int ni = 0; ni < 8; ni++) {
                    int np = ni >> 1, h = (ni & 1) * 2;
                    mma_f16(acc[mi][ni],
                            a[mi][0], a[mi][1], a[mi][2], a[mi][3],
                            b[np][h], b[np][h + 1]);
                }
        }
        __syncthreads();
    }

    const int g = lane >> 2;
    const int c = lane & 3;
#pragma unroll
    for (int mi = 0; mi < 2; mi++) {
        const int row0 = m0 + wm0 + mi * 16 + g;
        const int row1 = row0 + 8;
#pragma unroll
        for (int ni = 0; ni < 8; ni++) {
            const int col = z * SEC + wn0 + ni * 8 + 2 * c;
            const float bb0 = b1[col], bb1 = b1[col + 1];
            __half2 v0 = __floats2half2_rn(
                fmaxf(acc[mi][ni][0] + bb0, 0.0f),
                fmaxf(acc[mi][ni][1] + bb1, 0.0f));
            __half2 v1 = __floats2half2_rn(
                fmaxf(acc[mi][ni][2] + bb0, 0.0f),
                fmaxf(acc[mi][ni][3] + bb1, 0.0f));
            *reinterpret_cast<__half2*>(&g_h1h[(size_t)row0 * DIM + col]) = v0;
            *reinterpret_cast<__half2*>(&g_h1h[(size_t)row1 * DIM + col]) = v1;
        }
    }
}

// ---------------------------------------------------------------------------
// FUSED layers 2+3, v3: fp16 k-pair-packed smem operands to halve smem BW.
//   h1s/h2s layout: uint32 word [r][k2][c] = half2(val(k=2*k2), val(k=2*k2+1))
// 256 threads (32 c x 8 warps, 2 adjacent o-blocks per thread), 2 CTAs/SM.
// Per warp-row: 8 LDS.32 (iv) + 8 LDS.32 (hv) + 1 STS.32 (h2 pair) -> ~18
// wavefronts (was 36). FMA stays exact fp32.
// ---------------------------------------------------------------------------
#define FB_R    8
#define FB_BCNT 32

__global__ void __launch_bounds__(256, 2) fused23_kernel(
    const float* __restrict__ b2,
    const float* __restrict__ b3,
    float* __restrict__ out)
{
    const int cx   = blockIdx.x;              // 0..7
    const int tid  = threadIdx.x;
    const int c    = tid & 31;
    const int gq   = tid >> 5;                // warp id 0..7
    const int ccol = cx * 32 + c;

    // [r][k2][c] packed half2 words
    __shared__ uint32_t h1s[FB_R][8][32];     // 8 KB
    __shared__ uint32_t h2s[FB_R][8][32];     // 8 KB

    // Weights + biases in registers
    float w2[2][NBLK], w3[2][NBLK], bv2[2], bv3[2];
#pragma unroll
    for (int u = 0; u < 2; u++) {
        int o  = (gq * 2 + u) * SEC + ccol;
        bv2[u] = b2[o];
        bv3[u] = b3[o];
#pragma unroll
        for (int k = 0; k < NBLK; k++) {
            w2[u][k] = g_w2ct[k * DIM + o];
            w3[u][k] = g_w3ct[k * DIM + o];
        }
    }

    const int b0 = blockIdx.y * FB_BCNT;

    // staging map: thread = (r = tid>>5, k2 = (tid>>2)&7, c8i = tid&3)
    const int sr  = tid >> 5;
    const int sk2 = (tid >> 2) & 7;
    const int sc8 = (tid & 3) * 8;

    uint4 g0, g1;
    {
        const __half* p = &g_h1h[(size_t)(b0 + sr) * DIM +
                                 (2 * sk2) * SEC + cx * 32 + sc8];
        g0 = *reinterpret_cast<const uint4*>(p);
        g1 = *reinterpret_cast<const uint4*>(p + SEC);
    }

    for (int s = 0; s < FB_BCNT; s += FB_R) {
        // ---- stage: interleave k-even/k-odd halves -> packed words
        {
            const __half* e = reinterpret_cast<const __half*>(&g0);
            const __half* o = reinterpret_cast<const __half*>(&g1);
            uint32_t w[8];
#pragma unroll
            for (int j = 0; j < 8; j++) {
                __half2 p = __halves2half2(e[j], o[j]);
                w[j] = *reinterpret_cast<uint32_t*>(&p);
            }
            uint4* dst = reinterpret_cast<uint4*>(&h1s[sr][sk2][sc8]);
            dst[0] = make_uint4(w[0], w[1], w[2], w[3]);
            dst[1] = make_uint4(w[4], w[5], w[6], w[7]);
        }
        __syncthreads();                       // (1) h1s ready; h2s free

        // prefetch next slab (overlaps with layer-2 compute)
        if (s + FB_R < FB_BCNT) {
            const __half* p = &g_h1h[(size_t)(b0 + s + FB_R + sr) * DIM +
                                     (2 * sk2) * SEC + cx * 32 + sc8];
            g0 = *reinterpret_cast<const uint4*>(p);
            g1 = *reinterpret_cast<const uint4*>(p + SEC);
        }

        // ---- layer 2
#pragma unroll
        for (int r = 0; r < FB_R; r++) {
            float iv[NBLK];
#pragma unroll
            for (int k2 = 0; k2 < 8; k2++) {
                uint32_t wrd = h1s[r][k2][c];
                float2 f = __half22float2(*reinterpret_cast<__half2*>(&wrd));
                iv[2 * k2]     = f.x;
                iv[2 * k2 + 1] = f.y;
            }
            float a0 = bv2[0], a1 = bv2[1];
#pragma unroll
            for (int k = 0; k < NBLK; k++) {
                a0 = fmaf(w2[0][k], iv[k], a0);
                a1 = fmaf(w2[1][k], iv[k], a1);
            }
            __half2 hp = __floats2half2_rn(fmaxf(a0, 0.0f), fmaxf(a1, 0.0f));
            h2s[r][gq][c] = *reinterpret_cast<uint32_t*>(&hp);
        }
        __syncthreads();                       // (2) h2s ready; h1s free

        // ---- layer 3
#pragma unroll
        for (int r = 0; r < FB_R; r++) {
            float hv[NBLK];
#pragma unroll
            for (int k2 = 0; k2 < 8; k2++) {
                uint32_t wrd = h2s[r][k2][c];
                float2 f = __half22float2(*reinterpret_cast<__half2*>(&wrd));
                hv[2 * k2]     = f.x;
                hv[2 * k2 + 1] = f.y;
            }
            float a0 = bv3[0], a1 = bv3[1];
#pragma unroll
            for (int k = 0; k < NBLK; k++) {
                a0 = fmaf(w3[0][k], hv[k], a0);
                a1 = fmaf(w3[1][k], hv[k], a1);
            }
            size_t ob = (size_t)(b0 + s + r) * DIM;
            out[ob + (gq * 2 + 0) * SEC + ccol] = a0;
            out[ob + (gq * 2 + 1) * SEC + ccol] = a1;
        }
        // no barrier needed: next staging writes h1s, last read before (2)
    }
}

// ---------------------------------------------------------------------------
// Launch. Inputs (metadata order): x, W1, b1, W2, b2, W3, b3, m1, m2, m3
// ---------------------------------------------------------------------------
extern "C" void kernel_launch(void* const* d_in, const int* in_sizes, int n_in,
                              void* d_out, int out_size)
{
    const float* x  = (const float*)d_in[0];
    const float* W1 = (const float*)d_in[1];
    const float* b1 = (const float*)d_in[2];
    const float* W2 = (const float*)d_in[3];
    const float* b2 = (const float*)d_in[4];
    const float* W3 = (const float*)d_in[5];
    const float* b3 = (const float*)d_in[6];
    float* out = (float*)d_out;
    (void)in_sizes; (void)n_in; (void)out_size;

    static bool attr_set = false;
    if (!attr_set) {
        cudaFuncSetAttribute(layer1_mma_kernel,
                             cudaFuncAttributeMaxDynamicSharedMemorySize,
                             SMEM_L1);
        attr_set = true;
    }

    // 1) Prep: sparse tables + fp16 weight pack
    pack_kernel<<<64, 256>>>(W2, W3);
    pack_w1_kernel<<<(NBLK * SEC * 64) / 256, 256>>>(W1);

    // 2) Layer 1: fp16 GEMM (unchanged)
    layer1_mma_kernel<<<dim3(BATCH / 64, NBLK), 256, SMEM_L1>>>(x, b1);

    // 3) Layers 2+3 fused, v3 (fp16 packed smem)
    fused23_kernel<<<dim3(8, BATCH / FB_BCNT), 256>>>(b2, b3, out);
}